// round 6
// baseline (speedup 1.0000x reference)
#include <cuda_runtime.h>
#include <cuda_fp16.h>
#include <cstdint>

#define HHC 4096
#define OOC 4096
#define RRC 64

// smem pitches (in halves)
#define XP 40   // X tile [32][32] -> pitch 40
#define AP 40   // A tiles [64][32] -> pitch 40
#define TP 72   // T [32][64] -> pitch 72
#define BP 72   // B tiles [64][64] -> pitch 72

// smem layout (halves):
//   phase1 buf b @ b*6400 : X(1280) | Ah(2560) | Al(2560)   (2 bufs: 12800 h)
//   phase2 buf b @ b*9216 : Bh(4608) | Bl(4608)             (2 bufs: 18432 h, overlaps phase1)
//   Ts @ 18432 : 32*72 = 2304 h
// total halves = 20736 -> 41472 bytes
#define SMEM_TOTAL 41472

__device__ __forceinline__ void hmma16816(float* c,
                                          uint32_t a0, uint32_t a1, uint32_t a2, uint32_t a3,
                                          uint32_t b0, uint32_t b1) {
    asm volatile(
        "mma.sync.aligned.m16n8k16.row.col.f32.f16.f16.f32 "
        "{%0,%1,%2,%3}, {%4,%5,%6,%7}, {%8,%9}, {%0,%1,%2,%3};"
        : "+f"(c[0]), "+f"(c[1]), "+f"(c[2]), "+f"(c[3])
        : "r"(a0), "r"(a1), "r"(a2), "r"(a3), "r"(b0), "r"(b1));
}

__device__ __forceinline__ uint32_t h2u(__half2 h) {
    return *reinterpret_cast<uint32_t*>(&h);
}

__global__ __launch_bounds__(256, 3) void lora_fused(
    const float* __restrict__ result,
    const float* __restrict__ data,
    const float* __restrict__ mask,
    const float* __restrict__ lora_a,
    const float* __restrict__ lora_b,
    const float* __restrict__ scalings,
    float* __restrict__ out)
{
    extern __shared__ char smem[];
    __half* smh = reinterpret_cast<__half*>(smem);

    const int t    = threadIdx.x;
    const int w    = t >> 5;
    const int lane = t & 31;
    const int g    = lane >> 2;   // fragment row 0..7
    const int t4   = lane & 3;    // fragment k/col quad 0..3

    const int wm = w & 1;         // M slab (16 rows)
    const int wn = w >> 1;        // N quarter (16 cols)

    const int m0 = blockIdx.x * 32;
    const int n  = blockIdx.x >> 6;        // 64 CTAs per adapter
    const float sc = __ldg(scalings + n);

    const int row0 = wm * 16 + g;          // CTA-local m-row

    // ======================== PHASE 1 ========================
    // T[32,64] = (data*mask*sc)[32,4096] @ A^T, K-chunks of 32.
    float accT[2][4];
    #pragma unroll
    for (int j = 0; j < 2; j++)
        #pragma unroll
        for (int k = 0; k < 4; k++) accT[j][k] = 0.f;

    const float* dbase = data + (size_t)m0 * HHC;
    const float* mbase = mask + (size_t)m0 * HHC;
    const float* abase = lora_a + (size_t)n * RRC * HHC;

    // loader mappings
    const int xrow = t >> 3, xq = t & 7;   // X: 32 rows x 8 quads

    float4 dreg, mreg, areg[2];
    dreg = __ldcs((const float4*)(dbase + (size_t)xrow * HHC + xq * 4));
    mreg = __ldcs((const float4*)(mbase + (size_t)xrow * HHC + xq * 4));
    #pragma unroll
    for (int i = 0; i < 2; i++) {
        int idx = t + i * 256, row = idx >> 3, q = idx & 7;
        areg[i] = *(const float4*)(abase + (size_t)row * HHC + q * 4);
    }

    for (int ch = 0; ch < 128; ch++) {
        const int b = ch & 1;
        __half* Xs = smh + b * 6400;
        __half* Ah = smh + b * 6400 + 1280;
        __half* Al = smh + b * 6400 + 3840;

        // ---- STS X (fold mask & scaling) ----
        {
            float4 d4 = dreg, m4 = mreg;
            __half2 h0 = __floats2half2_rn(d4.x * m4.x * sc, d4.y * m4.y * sc);
            __half2 h1 = __floats2half2_rn(d4.z * m4.z * sc, d4.w * m4.w * sc);
            *(uint2*)(Xs + xrow * XP + xq * 4) = make_uint2(h2u(h0), h2u(h1));
        }
        // ---- STS A hi/lo ----
        #pragma unroll
        for (int i = 0; i < 2; i++) {
            int idx = t + i * 256, row = idx >> 3, q = idx & 7;
            float4 a4 = areg[i];
            __half2 ah0 = __floats2half2_rn(a4.x, a4.y);
            __half2 ah1 = __floats2half2_rn(a4.z, a4.w);
            float2 f0 = __half22float2(ah0), f1 = __half22float2(ah1);
            __half2 al0 = __floats2half2_rn(a4.x - f0.x, a4.y - f0.y);
            __half2 al1 = __floats2half2_rn(a4.z - f1.x, a4.w - f1.y);
            *(uint2*)(Ah + row * AP + q * 4) = make_uint2(h2u(ah0), h2u(ah1));
            *(uint2*)(Al + row * AP + q * 4) = make_uint2(h2u(al0), h2u(al1));
        }
        __syncthreads();

        // ---- prefetch next chunk ----
        if (ch + 1 < 128) {
            const int ho = (ch + 1) * 32;
            dreg = __ldcs((const float4*)(dbase + (size_t)xrow * HHC + ho + xq * 4));
            mreg = __ldcs((const float4*)(mbase + (size_t)xrow * HHC + ho + xq * 4));
            #pragma unroll
            for (int i = 0; i < 2; i++) {
                int idx = t + i * 256, row = idx >> 3, q = idx & 7;
                areg[i] = *(const float4*)(abase + (size_t)row * HHC + ho + q * 4);
            }
        }

        // ---- MMA: 2 k16 steps x 2 n-tiles x (hi+lo) ----
        #pragma unroll
        for (int s = 0; s < 2; s++) {
            const int kb = s * 16 + t4 * 2;
            uint32_t a0 = *(const uint32_t*)(Xs + row0 * XP + kb);
            uint32_t a1 = *(const uint32_t*)(Xs + (row0 + 8) * XP + kb);
            uint32_t a2 = *(const uint32_t*)(Xs + row0 * XP + kb + 8);
            uint32_t a3 = *(const uint32_t*)(Xs + (row0 + 8) * XP + kb + 8);
            #pragma unroll
            for (int j = 0; j < 2; j++) {
                const int nr = wn * 16 + j * 8 + g;
                uint32_t bh0 = *(const uint32_t*)(Ah + nr * AP + kb);
                uint32_t bh1 = *(const uint32_t*)(Ah + nr * AP + kb + 8);
                hmma16816(accT[j], a0, a1, a2, a3, bh0, bh1);
                uint32_t bl0 = *(const uint32_t*)(Al + nr * AP + kb);
                uint32_t bl1 = *(const uint32_t*)(Al + nr * AP + kb + 8);
                hmma16816(accT[j], a0, a1, a2, a3, bl0, bl1);
            }
        }
    }

    // ---- quantize T into smem ----
    __half* Ts = smh + 18432;
    #pragma unroll
    for (int j = 0; j < 2; j++) {
        const int c = wn * 16 + j * 8 + t4 * 2;
        __half2 h0 = __floats2half2_rn(accT[j][0], accT[j][1]);
        __half2 h1 = __floats2half2_rn(accT[j][2], accT[j][3]);
        *(uint32_t*)(Ts + row0 * TP + c)       = h2u(h0);
        *(uint32_t*)(Ts + (row0 + 8) * TP + c) = h2u(h1);
    }

    // ======================== PHASE 2 ========================
    // out[32, 4096] = result + T @ B^T, o-chunks of 64.
    const float* bbase = lora_b + (size_t)n * OOC * RRC;
    float4 breg[4];
    #pragma unroll
    for (int i = 0; i < 4; i++) {
        int idx = t + i * 256, row = idx >> 4, q = idx & 15;
        breg[i] = *(const float4*)(bbase + (size_t)row * RRC + q * 4);
    }
    __syncthreads();   // Ts visible; phase1 smem reads done before B STS

    for (int oc = 0; oc < 64; oc++) {
        const int b = oc & 1;
        __half* Bh = smh + b * 9216;
        __half* Bl = smh + b * 9216 + 4608;
        const int o0 = oc * 64;

        // ---- STS B hi/lo ----
        #pragma unroll
        for (int i = 0; i < 4; i++) {
            int idx = t + i * 256, row = idx >> 4, q = idx & 15;
            float4 a4 = breg[i];
            __half2 h0 = __floats2half2_rn(a4.x, a4.y);
            __half2 h1 = __floats2half2_rn(a4.z, a4.w);
            float2 f0 = __half22float2(h0), f1 = __half22float2(h1);
            __half2 l0 = __floats2half2_rn(a4.x - f0.x, a4.y - f0.y);
            __half2 l1 = __floats2half2_rn(a4.z - f1.x, a4.w - f1.y);
            *(uint2*)(Bh + row * BP + q * 4) = make_uint2(h2u(h0), h2u(h1));
            *(uint2*)(Bl + row * BP + q * 4) = make_uint2(h2u(l0), h2u(l1));
        }
        __syncthreads();

        // ---- prefetch next B chunk ----
        if (oc + 1 < 64) {
            const int on = (oc + 1) * 64;
            #pragma unroll
            for (int i = 0; i < 4; i++) {
                int idx = t + i * 256, row = idx >> 4, q = idx & 15;
                breg[i] = *(const float4*)(bbase + (size_t)(on + row) * RRC + q * 4);
            }
        }

        // ---- MMA: K = 64 = 4 k16 steps ----
        float acc[2][4];
        #pragma unroll
        for (int j = 0; j < 2; j++)
            #pragma unroll
            for (int k = 0; k < 4; k++) acc[j][k] = 0.f;

        #pragma unroll
        for (int s = 0; s < 4; s++) {
            const int kb = s * 16 + t4 * 2;
            uint32_t a0 = *(const uint32_t*)(Ts + row0 * TP + kb);
            uint32_t a1 = *(const uint32_t*)(Ts + (row0 + 8) * TP + kb);
            uint32_t a2 = *(const uint32_t*)(Ts + row0 * TP + kb + 8);
            uint32_t a3 = *(const uint32_t*)(Ts + (row0 + 8) * TP + kb + 8);
            #pragma unroll
            for (int j = 0; j < 2; j++) {
                const int nr = wn * 16 + j * 8 + g;
                uint32_t bh0 = *(const uint32_t*)(Bh + nr * BP + kb);
                uint32_t bh1 = *(const uint32_t*)(Bh + nr * BP + kb + 8);
                hmma16816(acc[j], a0, a1, a2, a3, bh0, bh1);
                uint32_t bl0 = *(const uint32_t*)(Bl + nr * BP + kb);
                uint32_t bl1 = *(const uint32_t*)(Bl + nr * BP + kb + 8);
                hmma16816(acc[j], a0, a1, a2, a3, bl0, bl1);
            }
        }

        // ---- epilogue: residual add + store ----
        #pragma unroll
        for (int j = 0; j < 2; j++) {
            const int ocol = o0 + wn * 16 + j * 8 + t4 * 2;
            size_t gi0 = (size_t)(m0 + row0) * OOC + ocol;
            size_t gi1 = (size_t)(m0 + row0 + 8) * OOC + ocol;
            float2 r0 = __ldcs((const float2*)(result + gi0));
            float2 r1 = __ldcs((const float2*)(result + gi1));
            __stcs((float2*)(out + gi0), make_float2(r0.x + acc[j][0], r0.y + acc[j][1]));
            __stcs((float2*)(out + gi1), make_float2(r1.x + acc[j][2], r1.y + acc[j][3]));
        }
    }
}

extern "C" void kernel_launch(void* const* d_in, const int* in_sizes, int n_in,
                              void* d_out, int out_size) {
    const float* result   = (const float*)d_in[0];
    const float* data     = (const float*)d_in[1];
    const float* mask     = (const float*)d_in[2];
    const float* lora_a   = (const float*)d_in[3];
    const float* lora_b   = (const float*)d_in[4];
    const float* scalings = (const float*)d_in[5];
    float* out = (float*)d_out;

    cudaFuncSetAttribute(lora_fused, cudaFuncAttributeMaxDynamicSharedMemorySize, SMEM_TOTAL);
    lora_fused<<<512, 256, SMEM_TOTAL>>>(result, data, mask, lora_a, lora_b, scalings, out);
}

// round 7
// speedup vs baseline: 1.5515x; 1.5515x over previous
#include <cuda_runtime.h>
#include <cuda_fp16.h>
#include <cstdint>

#define HHC 4096
#define OOC 4096
#define RRC 64

// pitches in halves
#define XP 72
#define AP 72
#define TP 72
#define BP 72

// smem (halves):
//   Xbuf[b]  = b*4608            [0,     9216)
//   Ahbuf[b] = 9216 + b*9216     [9216, 27648)   (Al = +4608)
//   Bhbuf[b] = b*9216            [0,    18432)   (phase2, overlaps phase1)
//   Ts       = 27648             [27648,32256)
#define SMEM_TOTAL (32256 * 2)

// pre-split fp16 hi/lo weights (4 MB each)
__device__ __half g_ah[(size_t)8 * RRC * HHC];
__device__ __half g_al[(size_t)8 * RRC * HHC];
__device__ __half g_bh[(size_t)8 * OOC * RRC];
__device__ __half g_bl[(size_t)8 * OOC * RRC];

__device__ __forceinline__ void hmma16816(float* c,
                                          uint32_t a0, uint32_t a1, uint32_t a2, uint32_t a3,
                                          uint32_t b0, uint32_t b1) {
    asm volatile(
        "mma.sync.aligned.m16n8k16.row.col.f32.f16.f16.f32 "
        "{%0,%1,%2,%3}, {%4,%5,%6,%7}, {%8,%9}, {%0,%1,%2,%3};"
        : "+f"(c[0]), "+f"(c[1]), "+f"(c[2]), "+f"(c[3])
        : "r"(a0), "r"(a1), "r"(a2), "r"(a3), "r"(b0), "r"(b1));
}

__device__ __forceinline__ uint32_t h2u(__half2 h) {
    return *reinterpret_cast<uint32_t*>(&h);
}

__device__ __forceinline__ void cp16(uint32_t dst, const void* src) {
    asm volatile("cp.async.cg.shared.global [%0], [%1], 16;"
                 :: "r"(dst), "l"(src) : "memory");
}
#define CP_COMMIT() asm volatile("cp.async.commit_group;" ::: "memory")
#define CP_WAIT0()  asm volatile("cp.async.wait_group 0;" ::: "memory")

// ---------------- prep: split lora_a / lora_b to fp16 hi/lo ----------------
__global__ __launch_bounds__(256) void lora_prep(const float* __restrict__ la,
                                                 const float* __restrict__ lb) {
    const size_t NA = (size_t)8 * RRC * HHC / 4;   // 524288 float4 per tensor
    size_t i = (size_t)blockIdx.x * 256 + threadIdx.x;
    const float4* src; uint2 *dh, *dl; size_t j;
    if (i < NA) { src = (const float4*)la; dh = (uint2*)g_ah; dl = (uint2*)g_al; j = i; }
    else        { src = (const float4*)lb; dh = (uint2*)g_bh; dl = (uint2*)g_bl; j = i - NA; }
    float4 a = src[j];
    __half2 h0 = __floats2half2_rn(a.x, a.y);
    __half2 h1 = __floats2half2_rn(a.z, a.w);
    float2 f0 = __half22float2(h0), f1 = __half22float2(h1);
    __half2 l0 = __floats2half2_rn(a.x - f0.x, a.y - f0.y);
    __half2 l1 = __floats2half2_rn(a.z - f1.x, a.w - f1.y);
    dh[j] = make_uint2(h2u(h0), h2u(h1));
    dl[j] = make_uint2(h2u(l0), h2u(l1));
}

// ---------------- fused LoRA ----------------
__global__ __launch_bounds__(256, 2) void lora_fused(
    const float* __restrict__ result,
    const float* __restrict__ data,
    const float* __restrict__ mask,
    const float* __restrict__ scalings,
    float* __restrict__ out)
{
    extern __shared__ char smem[];
    __half* smh = reinterpret_cast<__half*>(smem);
    const uint32_t sbase = (uint32_t)__cvta_generic_to_shared(smem);

    const int t    = threadIdx.x;
    const int w    = t >> 5;
    const int lane = t & 31;
    const int g    = lane >> 2;
    const int t4   = lane & 3;

    const int wm = w & 3;          // M slab (16 rows)
    const int wn = w >> 2;         // N half (32 cols)

    const int m0 = blockIdx.x * 64;
    const int n  = blockIdx.x >> 5;       // 32 CTAs per adapter
    const float sc = __ldg(scalings + n);

    const int row0 = wm * 16 + g;

    // ======================== PHASE 1 ========================
    // T[64,64] = (data*mask*sc)[64,4096] @ A^T,  K-chunks of 64
    float accT[4][4] = {};

    const float* dbase = data + (size_t)m0 * HHC;
    const float* mbase = mask + (size_t)m0 * HHC;
    const __half* ahb = g_ah + (size_t)n * RRC * HHC;
    const __half* alb = g_al + (size_t)n * RRC * HHC;

    const int xr = t >> 4, xq = t & 15;   // X loader: rows xr+16i, k-quad xq
    const int ar = t >> 3, aq = t & 7;    // A loader: rows ar+32i, 16B-chunk aq

    // preamble: cp.async A chunk 0 -> buf 0
    #pragma unroll
    for (int i = 0; i < 2; i++) {
        int row = ar + i * 32;
        uint32_t hoff = 9216u + (uint32_t)row * AP + aq * 8;
        cp16(sbase + hoff * 2, ahb + (size_t)row * HHC + aq * 8);
        cp16(sbase + (hoff + 4608u) * 2, alb + (size_t)row * HHC + aq * 8);
    }
    CP_COMMIT();

    float4 dreg[4], mreg[4];
    #pragma unroll
    for (int i = 0; i < 4; i++) {
        int row = xr + i * 16;
        dreg[i] = __ldcs((const float4*)(dbase + (size_t)row * HHC) + xq);
        mreg[i] = __ldcs((const float4*)(mbase + (size_t)row * HHC) + xq);
    }

    for (int ch = 0; ch < 64; ch++) {
        const int b = ch & 1;
        __half* Xs = smh + b * 4608;
        const __half* Ah = smh + 9216 + b * 9216;
        const __half* Al = Ah + 4608;

        // ---- STS X (fold mask & scaling, cvt fp16) ----
        #pragma unroll
        for (int i = 0; i < 4; i++) {
            int row = xr + i * 16;
            float4 d4 = dreg[i], m4 = mreg[i];
            __half2 h0 = __floats2half2_rn(d4.x * m4.x * sc, d4.y * m4.y * sc);
            __half2 h1 = __floats2half2_rn(d4.z * m4.z * sc, d4.w * m4.w * sc);
            *(uint2*)(Xs + row * XP + xq * 4) = make_uint2(h2u(h0), h2u(h1));
        }
        CP_WAIT0();
        __syncthreads();

        // ---- issue next A (safe: all readers of buf b^1 passed the sync) ----
        if (ch + 1 < 64) {
            const int ho = (ch + 1) * 64;
            #pragma unroll
            for (int i = 0; i < 2; i++) {
                int row = ar + i * 32;
                uint32_t hoff = 9216u + (uint32_t)(b ^ 1) * 9216u + (uint32_t)row * AP + aq * 8;
                cp16(sbase + hoff * 2, ahb + (size_t)row * HHC + ho + aq * 8);
                cp16(sbase + (hoff + 4608u) * 2, alb + (size_t)row * HHC + ho + aq * 8);
            }
            CP_COMMIT();
            #pragma unroll
            for (int i = 0; i < 4; i++) {
                int row = xr + i * 16;
                dreg[i] = __ldcs((const float4*)(dbase + (size_t)row * HHC + ho) + xq);
                mreg[i] = __ldcs((const float4*)(mbase + (size_t)row * HHC + ho) + xq);
            }
        }

        // ---- MMA: 4 k16 steps x 4 n-tiles x (hi+lo) ----
        #pragma unroll
        for (int s = 0; s < 4; s++) {
            const int kb = s * 16 + t4 * 2;
            uint32_t a0 = *(const uint32_t*)(Xs + row0 * XP + kb);
            uint32_t a1 = *(const uint32_t*)(Xs + (row0 + 8) * XP + kb);
            uint32_t a2 = *(const uint32_t*)(Xs + row0 * XP + kb + 8);
            uint32_t a3 = *(const uint32_t*)(Xs + (row0 + 8) * XP + kb + 8);
            #pragma unroll
            for (int j = 0; j < 4; j++) {
                const int nr = wn * 32 + j * 8 + g;
                uint32_t bh0 = *(const uint32_t*)(Ah + nr * AP + kb);
                uint32_t bh1 = *(const uint32_t*)(Ah + nr * AP + kb + 8);
                hmma16816(accT[j], a0, a1, a2, a3, bh0, bh1);
                uint32_t bl0 = *(const uint32_t*)(Al + nr * AP + kb);
                uint32_t bl1 = *(const uint32_t*)(Al + nr * AP + kb + 8);
                hmma16816(accT[j], a0, a1, a2, a3, bl0, bl1);
            }
        }
    }

    // ---- quantize T into smem ----
    __half* Ts = smh + 27648;
    #pragma unroll
    for (int j = 0; j < 4; j++) {
        const int c = wn * 32 + j * 8 + t4 * 2;
        __half2 h0 = __floats2half2_rn(accT[j][0], accT[j][1]);
        __half2 h1 = __floats2half2_rn(accT[j][2], accT[j][3]);
        *(uint32_t*)(Ts + row0 * TP + c)       = h2u(h0);
        *(uint32_t*)(Ts + (row0 + 8) * TP + c) = h2u(h1);
    }
    __syncthreads();   // phase1 smem reads done + Ts published, before B cp.async

    // ======================== PHASE 2 ========================
    // out[64, 4096] = result + T @ B^T,  o-chunks of 64
    const __half* bhb = g_bh + (size_t)n * OOC * RRC;
    const __half* blb = g_bl + (size_t)n * OOC * RRC;
    const int br = t >> 3, bq = t & 7;

    // preamble: cp.async B oc 0 -> buf 0
    #pragma unroll
    for (int i = 0; i < 2; i++) {
        int row = br + i * 32;
        uint32_t hoff = (uint32_t)row * BP + bq * 8;
        cp16(sbase + hoff * 2, bhb + (size_t)row * RRC + bq * 8);
        cp16(sbase + (hoff + 4608u) * 2, blb + (size_t)row * RRC + bq * 8);
    }
    CP_COMMIT();

    for (int oc = 0; oc < 64; oc++) {
        const int b = oc & 1;
        const __half* Bh = smh + b * 9216;
        const __half* Bl = Bh + 4608;
        const int o0 = oc * 64;

        CP_WAIT0();
        __syncthreads();

        if (oc + 1 < 64) {
            const int on = (oc + 1) * 64;
            #pragma unroll
            for (int i = 0; i < 2; i++) {
                int row = br + i * 32;
                uint32_t hoff = (uint32_t)(b ^ 1) * 9216u + (uint32_t)row * BP + bq * 8;
                cp16(sbase + hoff * 2, bhb + (size_t)(on + row) * RRC + bq * 8);
                cp16(sbase + (hoff + 4608u) * 2, blb + (size_t)(on + row) * RRC + bq * 8);
            }
            CP_COMMIT();
        }

        float acc[4][4] = {};
        #pragma unroll
        for (int s = 0; s < 4; s++) {
            const int kb = s * 16 + t4 * 2;
            uint32_t a0 = *(const uint32_t*)(Ts + row0 * TP + kb);
            uint32_t a1 = *(const uint32_t*)(Ts + (row0 + 8) * TP + kb);
            uint32_t a2 = *(const uint32_t*)(Ts + row0 * TP + kb + 8);
            uint32_t a3 = *(const uint32_t*)(Ts + (row0 + 8) * TP + kb + 8);
            #pragma unroll
            for (int j = 0; j < 4; j++) {
                const int nr = wn * 32 + j * 8 + g;
                uint32_t bh0 = *(const uint32_t*)(Bh + nr * BP + kb);
                uint32_t bh1 = *(const uint32_t*)(Bh + nr * BP + kb + 8);
                hmma16816(acc[j], a0, a1, a2, a3, bh0, bh1);
                uint32_t bl0 = *(const uint32_t*)(Bl + nr * BP + kb);
                uint32_t bl1 = *(const uint32_t*)(Bl + nr * BP + kb + 8);
                hmma16816(acc[j], a0, a1, a2, a3, bl0, bl1);
            }
        }

        // ---- epilogue: residual add + store ----
        #pragma unroll
        for (int j = 0; j < 4; j++) {
            const int ocol = o0 + wn * 32 + j * 8 + t4 * 2;
            size_t gi0 = (size_t)(m0 + row0) * OOC + ocol;
            size_t gi1 = (size_t)(m0 + row0 + 8) * OOC + ocol;
            float2 r0 = __ldcs((const float2*)(result + gi0));
            float2 r1 = __ldcs((const float2*)(result + gi1));
            __stcs((float2*)(out + gi0), make_float2(r0.x + acc[j][0], r0.y + acc[j][1]));
            __stcs((float2*)(out + gi1), make_float2(r1.x + acc[j][2], r1.y + acc[j][3]));
        }
    }
}

extern "C" void kernel_launch(void* const* d_in, const int* in_sizes, int n_in,
                              void* d_out, int out_size) {
    const float* result   = (const float*)d_in[0];
    const float* data     = (const float*)d_in[1];
    const float* mask     = (const float*)d_in[2];
    const float* lora_a   = (const float*)d_in[3];
    const float* lora_b   = (const float*)d_in[4];
    const float* scalings = (const float*)d_in[5];
    float* out = (float*)d_out;

    lora_prep<<<4096, 256>>>(lora_a, lora_b);

    cudaFuncSetAttribute(lora_fused, cudaFuncAttributeMaxDynamicSharedMemorySize, SMEM_TOTAL);
    lora_fused<<<256, 256, SMEM_TOTAL>>>(result, data, mask, scalings, out);
}

// round 8
// speedup vs baseline: 1.8204x; 1.1733x over previous
#include <cuda_runtime.h>
#include <cuda_fp16.h>
#include <cstdint>

#define HHC 4096
#define OOC 4096
#define RRC 64
#define PIT 72   // smem pitch in halves (144 B)

// smem (bytes):
//   Xbuf[b] = b*4608          [0, 9216)
//   Abuf[b] = 9216 + b*9216   [9216, 27648)
//   Bbuf[b] = b*9216          [0, 18432)   (phase2, overlaps X/A)
//   Ts      = 27648           [27648, 32256)
#define SMEM_TOTAL 32256

// pre-converted fp16 weights (4 MB each)
__device__ __half g_ah[(size_t)8 * RRC * HHC];
__device__ __half g_bh[(size_t)8 * OOC * RRC];

__device__ __forceinline__ void hmma16816(float* c,
                                          uint32_t a0, uint32_t a1, uint32_t a2, uint32_t a3,
                                          uint32_t b0, uint32_t b1) {
    asm volatile(
        "mma.sync.aligned.m16n8k16.row.col.f32.f16.f16.f32 "
        "{%0,%1,%2,%3}, {%4,%5,%6,%7}, {%8,%9}, {%0,%1,%2,%3};"
        : "+f"(c[0]), "+f"(c[1]), "+f"(c[2]), "+f"(c[3])
        : "r"(a0), "r"(a1), "r"(a2), "r"(a3), "r"(b0), "r"(b1));
}

__device__ __forceinline__ uint32_t h2u(__half2 h) {
    return *reinterpret_cast<uint32_t*>(&h);
}

__device__ __forceinline__ void cp16(uint32_t dst, const void* src) {
    asm volatile("cp.async.cg.shared.global [%0], [%1], 16;"
                 :: "r"(dst), "l"(src) : "memory");
}
#define CP_COMMIT() asm volatile("cp.async.commit_group;" ::: "memory")
#define CP_WAIT0()  asm volatile("cp.async.wait_group 0;" ::: "memory")

// ---------------- prep: convert lora_a / lora_b to fp16 ----------------
__global__ __launch_bounds__(256) void lora_prep(const float* __restrict__ la,
                                                 const float* __restrict__ lb) {
    const size_t NA = (size_t)8 * RRC * HHC / 4;   // 524288 float4 per tensor
    size_t i = (size_t)blockIdx.x * 256 + threadIdx.x;
    const float4* src; uint2* dh; size_t j;
    if (i < NA) { src = (const float4*)la; dh = (uint2*)g_ah; j = i; }
    else        { src = (const float4*)lb; dh = (uint2*)g_bh; j = i - NA; }
    float4 a = src[j];
    __half2 h0 = __floats2half2_rn(a.x, a.y);
    __half2 h1 = __floats2half2_rn(a.z, a.w);
    dh[j] = make_uint2(h2u(h0), h2u(h1));
}

// ---------------- fused LoRA ----------------
__global__ __launch_bounds__(256, 4) void lora_fused(
    const float* __restrict__ result,
    const float* __restrict__ data,
    const float* __restrict__ mask,
    const float* __restrict__ scalings,
    float* __restrict__ out)
{
    extern __shared__ char smem[];
    const uint32_t sbase = (uint32_t)__cvta_generic_to_shared(smem);

    const int t    = threadIdx.x;
    const int w    = t >> 5;
    const int lane = t & 31;
    const int g    = lane >> 2;
    const int t4   = lane & 3;

    const int wm = w & 1;          // M slab (16 rows of 32)
    const int wn = w >> 1;         // N slice (16 cols of 64)

    const int m0 = blockIdx.x * 32;
    const int n  = blockIdx.x >> 6;       // 64 CTAs per adapter
    const float sc = __ldg(scalings + n);

    const int row0 = wm * 16 + g;

    // ======================== PHASE 1 ========================
    // T[32,64] = (data*mask*sc)[32,4096] @ A^T,  K-chunks of 64
    float accT[2][4] = {};

    const float* dbase = data + (size_t)m0 * HHC;
    const float* mbase = mask + (size_t)m0 * HHC;
    const __half* ahb = g_ah + (size_t)n * RRC * HHC;

    const int xr = t >> 4, xq = t & 15;   // X loader: rows xr+16i, float4 xq
    const int ar = t >> 3, aq = t & 7;    // A loader: rows ar+32i, 16B chunk aq

    // preamble: cp.async A chunk 0 -> buf 0
    #pragma unroll
    for (int i = 0; i < 2; i++) {
        int row = ar + i * 32;
        cp16(sbase + 9216u + (uint32_t)row * 144u + aq * 16u,
             ahb + (size_t)row * HHC + aq * 8);
    }
    CP_COMMIT();

    float4 dreg[2], mreg[2];
    #pragma unroll
    for (int i = 0; i < 2; i++) {
        int row = xr + i * 16;
        dreg[i] = __ldcs((const float4*)(dbase + (size_t)row * HHC) + xq);
        mreg[i] = __ldcs((const float4*)(mbase + (size_t)row * HHC) + xq);
    }

    for (int ch = 0; ch < 64; ch++) {
        const int b = ch & 1;
        __half* Xs = (__half*)(smem + b * 4608);
        const __half* Ah = (const __half*)(smem + 9216 + b * 9216);

        // ---- STS X (fold mask & scaling, cvt fp16) ----
        #pragma unroll
        for (int i = 0; i < 2; i++) {
            int row = xr + i * 16;
            float4 d4 = dreg[i], m4 = mreg[i];
            __half2 h0 = __floats2half2_rn(d4.x * m4.x * sc, d4.y * m4.y * sc);
            __half2 h1 = __floats2half2_rn(d4.z * m4.z * sc, d4.w * m4.w * sc);
            *(uint2*)(Xs + row * PIT + xq * 4) = make_uint2(h2u(h0), h2u(h1));
        }
        CP_WAIT0();
        __syncthreads();

        // ---- issue next A + prefetch next X ----
        if (ch + 1 < 64) {
            const int ho = (ch + 1) * 64;
            #pragma unroll
            for (int i = 0; i < 2; i++) {
                int row = ar + i * 32;
                cp16(sbase + 9216u + (uint32_t)(b ^ 1) * 9216u + (uint32_t)row * 144u + aq * 16u,
                     ahb + (size_t)row * HHC + ho + aq * 8);
            }
            CP_COMMIT();
            #pragma unroll
            for (int i = 0; i < 2; i++) {
                int row = xr + i * 16;
                dreg[i] = __ldcs((const float4*)(dbase + (size_t)row * HHC + ho) + xq);
                mreg[i] = __ldcs((const float4*)(mbase + (size_t)row * HHC + ho) + xq);
            }
        }

        // ---- MMA: 4 k16 steps x 2 n-tiles ----
        #pragma unroll
        for (int s = 0; s < 4; s++) {
            const int kb = s * 16 + t4 * 2;
            uint32_t a0 = *(const uint32_t*)(Xs + row0 * PIT + kb);
            uint32_t a1 = *(const uint32_t*)(Xs + (row0 + 8) * PIT + kb);
            uint32_t a2 = *(const uint32_t*)(Xs + row0 * PIT + kb + 8);
            uint32_t a3 = *(const uint32_t*)(Xs + (row0 + 8) * PIT + kb + 8);
            #pragma unroll
            for (int j = 0; j < 2; j++) {
                const int nr = wn * 16 + j * 8 + g;
                uint32_t b0 = *(const uint32_t*)(Ah + nr * PIT + kb);
                uint32_t b1 = *(const uint32_t*)(Ah + nr * PIT + kb + 8);
                hmma16816(accT[j], a0, a1, a2, a3, b0, b1);
            }
        }
    }

    // ---- quantize T into smem ----
    __half* Ts = (__half*)(smem + 27648);
    #pragma unroll
    for (int j = 0; j < 2; j++) {
        const int c = wn * 16 + j * 8 + t4 * 2;
        __half2 h0 = __floats2half2_rn(accT[j][0], accT[j][1]);
        __half2 h1 = __floats2half2_rn(accT[j][2], accT[j][3]);
        *(uint32_t*)(Ts + row0 * PIT + c)       = h2u(h0);
        *(uint32_t*)(Ts + (row0 + 8) * PIT + c) = h2u(h1);
    }
    __syncthreads();   // Ts published; all phase1 smem reads done

    // ======================== PHASE 2 ========================
    // out[32, 4096] = result + T @ B^T,  o-chunks of 64
    const __half* bhb = g_bh + (size_t)n * OOC * RRC;
    const int br = t >> 3, bq = t & 7;

    // preamble: cp.async B oc 0 -> buf 0
    #pragma unroll
    for (int i = 0; i < 2; i++) {
        int row = br + i * 32;
        cp16(sbase + (uint32_t)row * 144u + bq * 16u,
             bhb + (size_t)row * RRC + bq * 8);
    }
    CP_COMMIT();

    for (int oc = 0; oc < 64; oc++) {
        const int b = oc & 1;
        const __half* Bh = (const __half*)(smem + b * 9216);
        const int o0 = oc * 64;

        CP_WAIT0();
        __syncthreads();

        if (oc + 1 < 64) {
            const int on = (oc + 1) * 64;
            #pragma unroll
            for (int i = 0; i < 2; i++) {
                int row = br + i * 32;
                cp16(sbase + (uint32_t)(b ^ 1) * 9216u + (uint32_t)row * 144u + bq * 16u,
                     bhb + (size_t)(on + row) * RRC + bq * 8);
            }
            CP_COMMIT();
        }

        float acc[2][4] = {};
        #pragma unroll
        for (int s = 0; s < 4; s++) {
            const int kb = s * 16 + t4 * 2;
            uint32_t a0 = *(const uint32_t*)(Ts + row0 * PIT + kb);
            uint32_t a1 = *(const uint32_t*)(Ts + (row0 + 8) * PIT + kb);
            uint32_t a2 = *(const uint32_t*)(Ts + row0 * PIT + kb + 8);
            uint32_t a3 = *(const uint32_t*)(Ts + (row0 + 8) * PIT + kb + 8);
            #pragma unroll
            for (int j = 0; j < 2; j++) {
                const int nr = wn * 16 + j * 8 + g;
                uint32_t b0 = *(const uint32_t*)(Bh + nr * PIT + kb);
                uint32_t b1 = *(const uint32_t*)(Bh + nr * PIT + kb + 8);
                hmma16816(acc[j], a0, a1, a2, a3, b0, b1);
            }
        }

        // ---- epilogue: residual add + store ----
        #pragma unroll
        for (int j = 0; j < 2; j++) {
            const int ocol = o0 + wn * 16 + j * 8 + t4 * 2;
            size_t gi0 = (size_t)(m0 + row0) * OOC + ocol;
            size_t gi1 = (size_t)(m0 + row0 + 8) * OOC + ocol;
            float2 r0 = __ldcs((const float2*)(result + gi0));
            float2 r1 = __ldcs((const float2*)(result + gi1));
            __stcs((float2*)(out + gi0), make_float2(r0.x + acc[j][0], r0.y + acc[j][1]));
            __stcs((float2*)(out + gi1), make_float2(r1.x + acc[j][2], r1.y + acc[j][3]));
        }
    }
}

extern "C" void kernel_launch(void* const* d_in, const int* in_sizes, int n_in,
                              void* d_out, int out_size) {
    const float* result   = (const float*)d_in[0];
    const float* data     = (const float*)d_in[1];
    const float* mask     = (const float*)d_in[2];
    const float* lora_a   = (const float*)d_in[3];
    const float* lora_b   = (const float*)d_in[4];
    const float* scalings = (const float*)d_in[5];
    float* out = (float*)d_out;

    lora_prep<<<4096, 256>>>(lora_a, lora_b);

    cudaFuncSetAttribute(lora_fused, cudaFuncAttributeMaxDynamicSharedMemorySize, SMEM_TOTAL);
    lora_fused<<<512, 256, SMEM_TOTAL>>>(result, data, mask, scalings, out);
}